// round 7
// baseline (speedup 1.0000x reference)
#include <cuda_runtime.h>
#include <cuda_bf16.h>
#include <cstdint>

// DifferentiableNLMS: B=32, T=2000, F=513, L=32, mu=0.1, eps=1e-8
// FOUR threads per (b,f) sequence: thread h owns taps [8h, 8h+8) and runs on
// a time-shifted x stream (shift 8*(3-h); zero-pad makes the shift exact), so
// all four threads execute identical code on a 4-pair (8-sample) ring with
// compile-time indices. Partial dots/norms/cross-correlations are summed over
// the lane quad with xor1+xor2 butterflies. Two-step lookahead + f32x2 FMAs.

#define NB 32
#define NT 2000
#define NF 513
#define NL 32
#define MU 0.1f
#define EPSV 1e-8f

#define NSEQ (NB * NF)        // 16416 sequences
#define NTHREAD (NSEQ * 4)    // 65664 threads = 2052 full warps
#define NSTEP 8               // steps per block (= one ring revolution)
#define NPB 4                 // lookahead-pairs per block

typedef unsigned long long u64;

__device__ __forceinline__ u64 ffma2(u64 a, u64 b, u64 c) {
    u64 d; asm("fma.rn.f32x2 %0, %1, %2, %3;" : "=l"(d) : "l"(a), "l"(b), "l"(c));
    return d;
}
__device__ __forceinline__ u64 fadd2(u64 a, u64 b) {
    u64 d; asm("add.rn.f32x2 %0, %1, %2;" : "=l"(d) : "l"(a), "l"(b));
    return d;
}
__device__ __forceinline__ u64 pack2(float lo, float hi) {
    u64 d; asm("mov.b64 %0, {%1, %2};" : "=l"(d) : "f"(lo), "f"(hi));
    return d;
}
__device__ __forceinline__ void unpack2(u64 v, float& lo, float& hi) {
    asm("mov.b64 {%0, %1}, %2;" : "=f"(lo), "=f"(hi) : "l"(v));
}
__device__ __forceinline__ u64 shflx(u64 v, int m) {
    return __shfl_xor_sync(0xFFFFFFFFu, v, m);
}

// Guarded prefetch (early blocks: shifted x indices can be negative -> 0).
__device__ __forceinline__ void prefetch_g(float (&x)[NSTEP], float (&y)[NSTEP],
                                           const float* __restrict__ xp,
                                           const float* __restrict__ yp,
                                           int t, int off)
{
#pragma unroll
    for (int u = 0; u < NSTEP; u++) {
        int ti = t + u - off;
        x[u] = (ti >= 0) ? __ldg(xp + (size_t)ti * NF) : 0.f;
        y[u] = __ldg(yp + (size_t)(t + u) * NF);
    }
}
// Unguarded prefetch (valid once t >= 24).
__device__ __forceinline__ void prefetch_u(float (&x)[NSTEP], float (&y)[NSTEP],
                                           const float* __restrict__ xp,
                                           const float* __restrict__ yp,
                                           int t, int off)
{
#pragma unroll
    for (int u = 0; u < NSTEP; u++) {
        x[u] = __ldg(xp + (size_t)(t + u - off) * NF);
        y[u] = __ldg(yp + (size_t)(t + u) * NF);
    }
}

__device__ __forceinline__ void run_block(
    u64 (&W2)[NPB], u64 (&P)[NPB], u64 (&Q)[NPB],
    float& S, float& CC, float& xlast,
    const float (&xb)[NSTEP], const float (&yb)[NSTEP],
    float* __restrict__ ep, int t0, bool writer)
{
    float minv[NSTEP];
    float ccs[NPB];
    float xm1_0 = xlast;

    // ---- Prologue: per-lane partial norms / cross-correlations (X-only) ----
    // Reads OLD ring slots (drops) before insertion; independent of W, so all
    // shuffles and MUFU.RCPs sit off the serial recursion's critical path.
    u64 spp[NPB];
    float cpl[NPB];
    {
        float Sl = S, CCl = CC;
#pragma unroll
        for (int p = 0; p < NPB; p++) {
            float a, b, bq, cq;
            unpack2(P[p], a, b);   // (x'_{t-9}, x'_{t-8})
            unpack2(Q[p], bq, cq); // (x'_{t-8}, x'_{t-7})
            float xm1 = p ? xb[2 * p - 1] : xm1_0;
            float x0 = xb[2 * p], x1 = xb[2 * p + 1];
            Sl = fmaf(x0, x0, Sl);
            Sl = fmaf(-b, b, Sl);
            float s0 = Sl;
            Sl = fmaf(x1, x1, Sl);
            Sl = fmaf(-cq, cq, Sl);
            spp[p] = pack2(s0, Sl);
            CCl = fmaf(xm1, x0, CCl);
            CCl = fmaf(x0, x1, CCl);
            CCl = fmaf(-a, b, CCl);
            CCl = fmaf(-bq, cq, CCl);
            cpl[p] = CCl;
        }
        S = Sl; CC = CCl;
    }
    // Quad-sum partial norms, compute step sizes (replicated in all lanes).
#pragma unroll
    for (int p = 0; p < NPB; p++) {
        u64 ss = fadd2(spp[p], shflx(spp[p], 1));
        ss = fadd2(ss, shflx(ss, 2));
        float s0, s1;
        unpack2(ss, s0, s1);
        minv[2 * p]     = __fdividef(MU, s0 + EPSV);
        minv[2 * p + 1] = __fdividef(MU, s1 + EPSV);
    }
    // Quad-sum partial cross-correlations (2 packed per shuffle round).
#pragma unroll
    for (int p = 0; p < NPB; p += 2) {
        u64 cv = pack2(cpl[p], cpl[p + 1]);
        cv = fadd2(cv, shflx(cv, 1));
        cv = fadd2(cv, shflx(cv, 2));
        unpack2(cv, ccs[p], ccs[p + 1]);
    }
    xlast = xb[NSTEP - 1];

    // ---- Serial recursion: 2 steps per iteration ----
#pragma unroll
    for (int p = 0; p < NPB; p++) {
        float xm1 = p ? xb[2 * p - 1] : xm1_0;
        float x0 = xb[2 * p], x1 = xb[2 * p + 1];
        P[p] = pack2(xm1, x0);  // slot holds (x'_{t-1}, x'_t)
        Q[p] = pack2(x0, x1);   // slot holds (x'_t, x'_{t+1})

        // Quarter-dots over own 4 pair-slots: window pair i -> slot (p+1+i)&3.
        u64 a0, a1, b0, b1;
        a0 = ffma2(W2[0], P[(p + 1) & 3], 0);
        a1 = ffma2(W2[1], P[(p + 2) & 3], 0);
        b0 = ffma2(W2[0], Q[(p + 1) & 3], 0);
        b1 = ffma2(W2[1], Q[(p + 2) & 3], 0);
        a0 = ffma2(W2[2], P[(p + 3) & 3], a0);
        a1 = ffma2(W2[3], P[(p + 4) & 3], a1);
        b0 = ffma2(W2[2], Q[(p + 3) & 3], b0);
        b1 = ffma2(W2[3], Q[(p + 4) & 3], b1);
        u64 ap = fadd2(a0, a1);
        u64 aq = fadd2(b0, b1);
        float plo, phi, qlo, qhi;
        unpack2(ap, plo, phi);
        unpack2(aq, qlo, qhi);
        // Sum quarters across the lane quad: two 64-bit butterflies.
        u64 pq = pack2(plo + phi, qlo + qhi);
        pq = fadd2(pq, shflx(pq, 1));
        pq = fadd2(pq, shflx(pq, 2));
        float pt, qt;
        unpack2(pq, pt, qt);

        float e0 = yb[2 * p] - pt;
        float c0 = e0 * minv[2 * p];
        float e1 = fmaf(-c0, ccs[p], yb[2 * p + 1] - qt);
        float c1 = e1 * minv[2 * p + 1];

        if (writer) {  // one writer lane per sequence
            ep[(size_t)(t0 + 2 * p) * NF] = e0;
            ep[(size_t)(t0 + 2 * p + 1) * NF] = e1;
        }

        u64 c0p = pack2(c0, c0);
        u64 c1p = pack2(c1, c1);
#pragma unroll
        for (int i = 0; i < NPB; i++) {
            W2[i] = ffma2(c1p, Q[(p + 1 + i) & 3],
                          ffma2(c0p, P[(p + 1 + i) & 3], W2[i]));
        }
    }
}

__global__ void __launch_bounds__(128, 4)
nlms_kernel(const float* __restrict__ X, const float* __restrict__ Y,
            const float* __restrict__ Wp, float* __restrict__ out,
            int write_w)
{
    int gtid = blockIdx.x * blockDim.x + threadIdx.x;
    if (gtid >= NTHREAD) return;
    int h = gtid & 3;          // tap-quarter owner (lane quad)
    int seq = gtid >> 2;
    int b = seq / NF;
    int f = seq - b * NF;
    int off = 8 * (3 - h);     // time shift of this thread's x stream

    size_t base = (size_t)b * NT * NF + f;
    const float* xp = X + base;
    const float* yp = Y + base;
    float* ep = out + base;    // E_hat_mag at offset 0
    bool writer = (h == 3);

    u64 W2[NPB], P[NPB], Q[NPB];
#pragma unroll
    for (int i = 0; i < NPB; i++) {
        int j = 8 * h + 2 * i;
        float w0 = Wp[((size_t)b * NL + j) * NF + f];
        float w1 = Wp[((size_t)b * NL + j + 1) * NF + f];
        W2[i] = pack2(w0, w1);
        P[i] = 0;  // zero pad: window starts empty
        Q[i] = 0;
    }
    float S = 0.f, CC = 0.f, xlast = 0.f;

    float xA[NSTEP], yA[NSTEP], xB[NSTEP], yB[NSTEP];
    prefetch_g(xA, yA, xp, yp, 0, off);

    int t0 = 0;
    // Peel: blocks 0..3 (t < 32) with guarded prefetch (shifted idx < 0).
#pragma unroll 1
    for (int dd = 0; dd < 2; dd++) {
        prefetch_g(xB, yB, xp, yp, t0 + NSTEP, off);
        run_block(W2, P, Q, S, CC, xlast, xA, yA, ep, t0, writer);
        t0 += NSTEP;
        prefetch_g(xA, yA, xp, yp, t0 + NSTEP, off);
        run_block(W2, P, Q, S, CC, xlast, xB, yB, ep, t0, writer);
        t0 += NSTEP;
    }
    // Main: blocks 4..249 = 123 double-iterations, unguarded prefetch.
#pragma unroll 1
    for (int dd = 0; dd < 123; dd++) {
        prefetch_u(xB, yB, xp, yp, t0 + NSTEP, off);
        run_block(W2, P, Q, S, CC, xlast, xA, yA, ep, t0, writer);
        t0 += NSTEP;
        int tn = (t0 + NSTEP < NT) ? (t0 + NSTEP) : (NT - NSTEP);  // clamp final
        prefetch_u(xA, yA, xp, yp, tn, off);
        run_block(W2, P, Q, S, CC, xlast, xB, yB, ep, t0, writer);
        t0 += NSTEP;
    }

    if (write_w) {
        float* wf = out + (size_t)NB * NT * NF;  // W_final after E
#pragma unroll
        for (int i = 0; i < NPB; i++) {
            int j = 8 * h + 2 * i;
            float w0, w1;
            unpack2(W2[i], w0, w1);
            wf[((size_t)b * NL + j) * NF + f] = w0;
            wf[((size_t)b * NL + j + 1) * NF + f] = w1;
        }
    }
}

extern "C" void kernel_launch(void* const* d_in, const int* in_sizes, int n_in,
                              void* d_out, int out_size)
{
    const float* X  = (const float*)d_in[0];  // X_hat_mag [B,T,F]
    const float* Y  = (const float*)d_in[1];  // Y_mag     [B,T,F]
    const float* Wp = (const float*)d_in[2];  // W_prev    [B,L,F]
    float* out = (float*)d_out;

    long long need = (long long)NB * NT * NF + (long long)NB * NL * NF;
    int write_w = ((long long)out_size >= need) ? 1 : 0;

    // 65664 threads (2052 full warps), 128/block -> 513 blocks, one wave
    // at 4 blocks/SM (regs capped at 128 by launch_bounds).
    nlms_kernel<<<513, 128>>>(X, Y, Wp, out, write_w);
}

// round 8
// speedup vs baseline: 1.0030x; 1.0030x over previous
#include <cuda_runtime.h>
#include <cuda_bf16.h>
#include <cstdint>

// DifferentiableNLMS: B=32, T=2000, F=513, L=32, mu=0.1, eps=1e-8
// FOUR threads per (b,f) sequence: thread h owns taps [8h, 8h+8) and runs on
// a time-shifted x stream (shift 8*(3-h); zero-pad makes the shift exact), so
// all four threads execute identical code on a 4-pair (8-sample) ring with
// compile-time indices. Partial dots/norms/cross-correlations are summed over
// the lane quad with xor1+xor2 butterflies. Two-step lookahead + f32x2 FMAs.

#define NB 32
#define NT 2000
#define NF 513
#define NL 32
#define MU 0.1f
#define EPSV 1e-8f

#define NSEQ (NB * NF)        // 16416 sequences
#define NTHREAD (NSEQ * 4)    // 65664 threads = 2052 full warps
#define NSTEP 8               // steps per block (= one ring revolution)
#define NPB 4                 // lookahead-pairs per block

typedef unsigned long long u64;

__device__ __forceinline__ u64 ffma2(u64 a, u64 b, u64 c) {
    u64 d; asm("fma.rn.f32x2 %0, %1, %2, %3;" : "=l"(d) : "l"(a), "l"(b), "l"(c));
    return d;
}
__device__ __forceinline__ u64 fadd2(u64 a, u64 b) {
    u64 d; asm("add.rn.f32x2 %0, %1, %2;" : "=l"(d) : "l"(a), "l"(b));
    return d;
}
__device__ __forceinline__ u64 pack2(float lo, float hi) {
    u64 d; asm("mov.b64 %0, {%1, %2};" : "=l"(d) : "f"(lo), "f"(hi));
    return d;
}
__device__ __forceinline__ void unpack2(u64 v, float& lo, float& hi) {
    asm("mov.b64 {%0, %1}, %2;" : "=f"(lo), "=f"(hi) : "l"(v));
}
__device__ __forceinline__ u64 shflx(u64 v, int m) {
    return __shfl_xor_sync(0xFFFFFFFFu, v, m);
}

// Guarded prefetch (early blocks: shifted x indices can be negative -> 0).
__device__ __forceinline__ void prefetch_g(float (&x)[NSTEP], float (&y)[NSTEP],
                                           const float* __restrict__ xp,
                                           const float* __restrict__ yp,
                                           int t, int off)
{
#pragma unroll
    for (int u = 0; u < NSTEP; u++) {
        int ti = t + u - off;
        x[u] = (ti >= 0) ? __ldg(xp + (size_t)ti * NF) : 0.f;
        y[u] = __ldg(yp + (size_t)(t + u) * NF);
    }
}
// Unguarded prefetch (valid once t >= 24).
__device__ __forceinline__ void prefetch_u(float (&x)[NSTEP], float (&y)[NSTEP],
                                           const float* __restrict__ xp,
                                           const float* __restrict__ yp,
                                           int t, int off)
{
#pragma unroll
    for (int u = 0; u < NSTEP; u++) {
        x[u] = __ldg(xp + (size_t)(t + u - off) * NF);
        y[u] = __ldg(yp + (size_t)(t + u) * NF);
    }
}

__device__ __forceinline__ void run_block(
    u64 (&W2)[NPB], u64 (&P)[NPB], u64 (&Q)[NPB],
    float& S, float& CC, float& xlast,
    const float (&xb)[NSTEP], const float (&yb)[NSTEP],
    float* __restrict__ ep, int t0, bool writer)
{
    float minv[NSTEP];
    float ccs[NPB];
    float xm1_0 = xlast;

    // ---- Prologue: per-lane partial norms / cross-correlations (X-only) ----
    // Reads OLD ring slots (drops) before insertion; independent of W, so all
    // shuffles and MUFU.RCPs sit off the serial recursion's critical path.
    u64 spp[NPB];
    float cpl[NPB];
    {
        float Sl = S, CCl = CC;
#pragma unroll
        for (int p = 0; p < NPB; p++) {
            float a, b, bq, cq;
            unpack2(P[p], a, b);   // (x'_{t-9}, x'_{t-8})
            unpack2(Q[p], bq, cq); // (x'_{t-8}, x'_{t-7})
            float xm1 = p ? xb[2 * p - 1] : xm1_0;
            float x0 = xb[2 * p], x1 = xb[2 * p + 1];
            Sl = fmaf(x0, x0, Sl);
            Sl = fmaf(-b, b, Sl);
            float s0 = Sl;
            Sl = fmaf(x1, x1, Sl);
            Sl = fmaf(-cq, cq, Sl);
            spp[p] = pack2(s0, Sl);
            CCl = fmaf(xm1, x0, CCl);
            CCl = fmaf(x0, x1, CCl);
            CCl = fmaf(-a, b, CCl);
            CCl = fmaf(-bq, cq, CCl);
            cpl[p] = CCl;
        }
        S = Sl; CC = CCl;
    }
    // Quad-sum partial norms, compute step sizes (replicated in all lanes).
#pragma unroll
    for (int p = 0; p < NPB; p++) {
        u64 ss = fadd2(spp[p], shflx(spp[p], 1));
        ss = fadd2(ss, shflx(ss, 2));
        float s0, s1;
        unpack2(ss, s0, s1);
        minv[2 * p]     = __fdividef(MU, s0 + EPSV);
        minv[2 * p + 1] = __fdividef(MU, s1 + EPSV);
    }
    // Quad-sum partial cross-correlations (2 packed per shuffle round).
#pragma unroll
    for (int p = 0; p < NPB; p += 2) {
        u64 cv = pack2(cpl[p], cpl[p + 1]);
        cv = fadd2(cv, shflx(cv, 1));
        cv = fadd2(cv, shflx(cv, 2));
        unpack2(cv, ccs[p], ccs[p + 1]);
    }
    xlast = xb[NSTEP - 1];

    // ---- Serial recursion: 2 steps per iteration ----
#pragma unroll
    for (int p = 0; p < NPB; p++) {
        float xm1 = p ? xb[2 * p - 1] : xm1_0;
        float x0 = xb[2 * p], x1 = xb[2 * p + 1];
        P[p] = pack2(xm1, x0);  // slot holds (x'_{t-1}, x'_t)
        Q[p] = pack2(x0, x1);   // slot holds (x'_t, x'_{t+1})

        // Quarter-dots over own 4 pair-slots: window pair i -> slot (p+1+i)&3.
        u64 a0, a1, b0, b1;
        a0 = ffma2(W2[0], P[(p + 1) & 3], 0);
        a1 = ffma2(W2[1], P[(p + 2) & 3], 0);
        b0 = ffma2(W2[0], Q[(p + 1) & 3], 0);
        b1 = ffma2(W2[1], Q[(p + 2) & 3], 0);
        a0 = ffma2(W2[2], P[(p + 3) & 3], a0);
        a1 = ffma2(W2[3], P[(p + 4) & 3], a1);
        b0 = ffma2(W2[2], Q[(p + 3) & 3], b0);
        b1 = ffma2(W2[3], Q[(p + 4) & 3], b1);
        u64 ap = fadd2(a0, a1);
        u64 aq = fadd2(b0, b1);
        float plo, phi, qlo, qhi;
        unpack2(ap, plo, phi);
        unpack2(aq, qlo, qhi);
        // Sum quarters across the lane quad: two 64-bit butterflies.
        u64 pq = pack2(plo + phi, qlo + qhi);
        pq = fadd2(pq, shflx(pq, 1));
        pq = fadd2(pq, shflx(pq, 2));
        float pt, qt;
        unpack2(pq, pt, qt);

        float e0 = yb[2 * p] - pt;
        float c0 = e0 * minv[2 * p];
        float e1 = fmaf(-c0, ccs[p], yb[2 * p + 1] - qt);
        float c1 = e1 * minv[2 * p + 1];

        if (writer) {  // one writer lane per sequence
            ep[(size_t)(t0 + 2 * p) * NF] = e0;
            ep[(size_t)(t0 + 2 * p + 1) * NF] = e1;
        }

        u64 c0p = pack2(c0, c0);
        u64 c1p = pack2(c1, c1);
#pragma unroll
        for (int i = 0; i < NPB; i++) {
            W2[i] = ffma2(c1p, Q[(p + 1 + i) & 3],
                          ffma2(c0p, P[(p + 1 + i) & 3], W2[i]));
        }
    }
}

__global__ void __launch_bounds__(128, 4)
nlms_kernel(const float* __restrict__ X, const float* __restrict__ Y,
            const float* __restrict__ Wp, float* __restrict__ out,
            int write_w)
{
    int gtid = blockIdx.x * blockDim.x + threadIdx.x;
    if (gtid >= NTHREAD) return;
    int h = gtid & 3;          // tap-quarter owner (lane quad)
    int seq = gtid >> 2;
    int b = seq / NF;
    int f = seq - b * NF;
    int off = 8 * (3 - h);     // time shift of this thread's x stream

    size_t base = (size_t)b * NT * NF + f;
    const float* xp = X + base;
    const float* yp = Y + base;
    float* ep = out + base;    // E_hat_mag at offset 0
    bool writer = (h == 3);

    u64 W2[NPB], P[NPB], Q[NPB];
#pragma unroll
    for (int i = 0; i < NPB; i++) {
        int j = 8 * h + 2 * i;
        float w0 = Wp[((size_t)b * NL + j) * NF + f];
        float w1 = Wp[((size_t)b * NL + j + 1) * NF + f];
        W2[i] = pack2(w0, w1);
        P[i] = 0;  // zero pad: window starts empty
        Q[i] = 0;
    }
    float S = 0.f, CC = 0.f, xlast = 0.f;

    float xA[NSTEP], yA[NSTEP], xB[NSTEP], yB[NSTEP];
    prefetch_g(xA, yA, xp, yp, 0, off);

    int t0 = 0;
    // Peel: blocks 0..3 (t < 32) with guarded prefetch (shifted idx < 0).
#pragma unroll 1
    for (int dd = 0; dd < 2; dd++) {
        prefetch_g(xB, yB, xp, yp, t0 + NSTEP, off);
        run_block(W2, P, Q, S, CC, xlast, xA, yA, ep, t0, writer);
        t0 += NSTEP;
        prefetch_g(xA, yA, xp, yp, t0 + NSTEP, off);
        run_block(W2, P, Q, S, CC, xlast, xB, yB, ep, t0, writer);
        t0 += NSTEP;
    }
    // Main: blocks 4..249 = 123 double-iterations, unguarded prefetch.
#pragma unroll 1
    for (int dd = 0; dd < 123; dd++) {
        prefetch_u(xB, yB, xp, yp, t0 + NSTEP, off);
        run_block(W2, P, Q, S, CC, xlast, xA, yA, ep, t0, writer);
        t0 += NSTEP;
        int tn = (t0 + NSTEP < NT) ? (t0 + NSTEP) : (NT - NSTEP);  // clamp final
        prefetch_u(xA, yA, xp, yp, tn, off);
        run_block(W2, P, Q, S, CC, xlast, xB, yB, ep, t0, writer);
        t0 += NSTEP;
    }

    if (write_w) {
        float* wf = out + (size_t)NB * NT * NF;  // W_final after E
#pragma unroll
        for (int i = 0; i < NPB; i++) {
            int j = 8 * h + 2 * i;
            float w0, w1;
            unpack2(W2[i], w0, w1);
            wf[((size_t)b * NL + j) * NF + f] = w0;
            wf[((size_t)b * NL + j + 1) * NF + f] = w1;
        }
    }
}

extern "C" void kernel_launch(void* const* d_in, const int* in_sizes, int n_in,
                              void* d_out, int out_size)
{
    const float* X  = (const float*)d_in[0];  // X_hat_mag [B,T,F]
    const float* Y  = (const float*)d_in[1];  // Y_mag     [B,T,F]
    const float* Wp = (const float*)d_in[2];  // W_prev    [B,L,F]
    float* out = (float*)d_out;

    long long need = (long long)NB * NT * NF + (long long)NB * NL * NF;
    int write_w = ((long long)out_size >= need) ? 1 : 0;

    // 65664 threads (2052 full warps), 128/block -> 513 blocks, one wave
    // at 4 blocks/SM (regs capped at 128 by launch_bounds).
    nlms_kernel<<<513, 128>>>(X, Y, Wp, out, write_w);
}

// round 9
// speedup vs baseline: 1.1739x; 1.1703x over previous
#include <cuda_runtime.h>
#include <cuda_bf16.h>
#include <cstdint>

// DifferentiableNLMS: B=32, T=2000, F=513, L=32, mu=0.1, eps=1e-8
// Two threads per (b,f): lane h owns taps [16h,16h+16) on a time-shifted x
// stream (h=0 shifted -16; zero-pad makes it exact). Exact 4-step block
// recursion with incrementally-maintained lag correlations D1,D2,D3; one
// shuffle-reduce stage per 4 steps. Packed f32x2 FMAs throughout.

#define NB 32
#define NT 2000
#define NF 513
#define NL 32
#define MU 0.1f
#define EPSV 1e-8f

#define NSEQ (NB * NF)
#define NTHREAD (NSEQ * 2)   // 32832 = 1026 full warps
#define NSTEP 16

typedef unsigned long long u64;

__device__ __forceinline__ u64 ffma2(u64 a, u64 b, u64 c) {
    u64 d; asm("fma.rn.f32x2 %0, %1, %2, %3;" : "=l"(d) : "l"(a), "l"(b), "l"(c));
    return d;
}
__device__ __forceinline__ u64 fadd2(u64 a, u64 b) {
    u64 d; asm("add.rn.f32x2 %0, %1, %2;" : "=l"(d) : "l"(a), "l"(b));
    return d;
}
__device__ __forceinline__ u64 pack2(float lo, float hi) {
    u64 d; asm("mov.b64 %0, {%1, %2};" : "=l"(d) : "f"(lo), "f"(hi));
    return d;
}
__device__ __forceinline__ void unpack2(u64 v, float& lo, float& hi) {
    asm("mov.b64 {%0, %1}, %2;" : "=f"(lo), "=f"(hi) : "l"(v));
}
__device__ __forceinline__ u64 shflx(u64 v) {
    return __shfl_xor_sync(0xFFFFFFFFu, v, 1);
}

__device__ __forceinline__ void pf_g(float (&x)[16], float (&y)[16],
                                     const float* __restrict__ xp,
                                     const float* __restrict__ yp, int t, int off)
{
#pragma unroll
    for (int u = 0; u < 16; u++) {
        int ti = t + u - off;
        x[u] = (ti >= 0) ? __ldg(xp + (size_t)ti * NF) : 0.f;
        y[u] = __ldg(yp + (size_t)(t + u) * NF);
    }
}
__device__ __forceinline__ void pf_u(float (&x)[16], float (&y)[16],
                                     const float* __restrict__ xp,
                                     const float* __restrict__ yp, int t, int off)
{
#pragma unroll
    for (int u = 0; u < 16; u++) {
        x[u] = __ldg(xp + (size_t)(t + u - off) * NF);
        y[u] = __ldg(yp + (size_t)(t + u) * NF);
    }
}

struct Carry { float xl1, xl2, xl3, c33, c34, c35; };

// Prologue: odd lane advances S (lag0 norm), D1,D2,D3 (lags) over the block
// using current xb and old2 (= x block from 32 steps back); samples what the
// 4 groups need; broadcasts to the even lane. All X-only, off the W chain.
__device__ __forceinline__ void prologue(
    const float (&xb)[16], const float (&o2)[16],
    float& S, float& G1, float& G2, float& G3, Carry& cr,
    float (&minv)[16], float (&g1s)[12], float (&g2s)[8], float (&g3s)[4], int h)
{
#pragma unroll
    for (int u = 0; u < 16; u++) {
        float xt = xb[u], d32 = o2[u];
        S = fmaf(xt, xt, S);
        S = fmaf(-d32, d32, S);
        minv[u] = __fdividef(MU, S + EPSV);
        float xm1 = (u >= 1) ? xb[u - 1] : cr.xl1;
        float d33 = (u >= 1) ? o2[u - 1] : cr.c33;
        G1 = fmaf(xm1, xt, G1);
        G1 = fmaf(-d33, d32, G1);
        if ((u & 3) != 0) g1s[3 * (u >> 2) + (u & 3) - 1] = G1;
        float xm2 = (u >= 2) ? xb[u - 2] : ((u == 1) ? cr.xl1 : cr.xl2);
        float d34 = (u >= 2) ? o2[u - 2] : ((u == 1) ? cr.c33 : cr.c34);
        G2 = fmaf(xm2, xt, G2);
        G2 = fmaf(-d34, d32, G2);
        if ((u & 3) >= 2) g2s[2 * (u >> 2) + (u & 3) - 2] = G2;
        float xm3 = (u >= 3) ? xb[u - 3] : ((u == 2) ? cr.xl1 : ((u == 1) ? cr.xl2 : cr.xl3));
        float d35 = (u >= 3) ? o2[u - 3] : ((u == 2) ? cr.c33 : ((u == 1) ? cr.c34 : cr.c35));
        G3 = fmaf(xm3, xt, G3);
        G3 = fmaf(-d35, d32, G3);
        if ((u & 3) == 3) g3s[u >> 2] = G3;
    }
    // Broadcast odd lane's values to even lane (packed, 2 per shuffle).
#pragma unroll
    for (int k = 0; k < 8; k++) {
        u64 v = pack2(minv[2 * k], minv[2 * k + 1]);
        u64 o = shflx(v); v = h ? v : o;
        unpack2(v, minv[2 * k], minv[2 * k + 1]);
    }
#pragma unroll
    for (int k = 0; k < 6; k++) {
        u64 v = pack2(g1s[2 * k], g1s[2 * k + 1]);
        u64 o = shflx(v); v = h ? v : o;
        unpack2(v, g1s[2 * k], g1s[2 * k + 1]);
    }
#pragma unroll
    for (int k = 0; k < 4; k++) {
        u64 v = pack2(g2s[2 * k], g2s[2 * k + 1]);
        u64 o = shflx(v); v = h ? v : o;
        unpack2(v, g2s[2 * k], g2s[2 * k + 1]);
    }
    {
        u64 v = pack2(g3s[0], g3s[1]);
        u64 o = shflx(v); v = h ? v : o;
        unpack2(v, g3s[0], g3s[1]);
        v = pack2(g3s[2], g3s[3]);
        o = shflx(v); v = h ? v : o;
        unpack2(v, g3s[2], g3s[3]);
    }
}

// Serial recursion: 4 groups of 4 steps; one shuffle stage per group.
__device__ __forceinline__ void serial4(
    u64 (&W2)[8], u64 (&P)[8], u64 (&Q)[8],
    const float (&xb)[16], const float (&yb)[16],
    const float (&minv)[16], const float (&g1s)[12],
    const float (&g2s)[8], const float (&g3s)[4],
    float xl1, float* __restrict__ ep, int t0, int h)
{
#pragma unroll
    for (int g = 0; g < 4; g++) {
        const int p = 2 * g;
        float xm1 = g ? xb[4 * g - 1] : xl1;
        float x0 = xb[4 * g], x1 = xb[4 * g + 1];
        float x2 = xb[4 * g + 2], x3 = xb[4 * g + 3];

        u64 oldP1 = P[(p + 1) & 7], oldQ1 = Q[(p + 1) & 7];
        P[p] = pack2(xm1, x0);
        Q[p] = pack2(x0, x1);

        // d0 = W.Xw_t, d1 = W.Xw_{t+1} (slot p+1 still old = window pair 0).
        u64 a0 = 0, a1 = 0, b0 = 0, b1 = 0;
#pragma unroll
        for (int i = 0; i < 8; i += 2) {
            a0 = ffma2(W2[i],     P[(p + 1 + i) & 7], a0);
            a1 = ffma2(W2[i + 1], P[(p + 2 + i) & 7], a1);
            b0 = ffma2(W2[i],     Q[(p + 1 + i) & 7], b0);
            b1 = ffma2(W2[i + 1], Q[(p + 2 + i) & 7], b1);
        }
        P[(p + 1) & 7] = pack2(x1, x2);
        Q[(p + 1) & 7] = pack2(x2, x3);
        // d2 = W.Xw_{t+2}, d3 = W.Xw_{t+3} (windows start at slot p+2).
        u64 c0a = 0, c1a = 0, d0a = 0, d1a = 0;
#pragma unroll
        for (int i = 0; i < 8; i += 2) {
            c0a = ffma2(W2[i],     P[(p + 2 + i) & 7], c0a);
            c1a = ffma2(W2[i + 1], P[(p + 3 + i) & 7], c1a);
            d0a = ffma2(W2[i],     Q[(p + 2 + i) & 7], d0a);
            d1a = ffma2(W2[i + 1], Q[(p + 3 + i) & 7], d1a);
        }
        u64 sa = fadd2(a0, a1), sb = fadd2(b0, b1);
        u64 sc = fadd2(c0a, c1a), sd = fadd2(d0a, d1a);
        float alo, ahi, blo, bhi, clo, chi, dlo, dhi;
        unpack2(sa, alo, ahi); unpack2(sb, blo, bhi);
        unpack2(sc, clo, chi); unpack2(sd, dlo, dhi);
        u64 v01 = pack2(alo + ahi, blo + bhi);
        u64 v23 = pack2(clo + chi, dlo + dhi);
        v01 = fadd2(v01, shflx(v01));          // two independent shuffles:
        v23 = fadd2(v23, shflx(v23));          // one latency stage
        float d0, d1, d2, d3;
        unpack2(v01, d0, d1); unpack2(v23, d2, d3);

        float e0 = yb[4 * g] - d0;
        float c0 = e0 * minv[4 * g];
        float e1 = fmaf(-c0, g1s[3 * g], yb[4 * g + 1] - d1);
        float c1 = e1 * minv[4 * g + 1];
        float e2 = fmaf(-c1, g1s[3 * g + 1],
                   fmaf(-c0, g2s[2 * g], yb[4 * g + 2] - d2));
        float c2 = e2 * minv[4 * g + 2];
        float e3 = fmaf(-c2, g1s[3 * g + 2],
                   fmaf(-c1, g2s[2 * g + 1],
                   fmaf(-c0, g3s[g], yb[4 * g + 3] - d3)));
        float c3 = e3 * minv[4 * g + 3];

        if (h) {
            ep[(size_t)(t0 + 4 * g) * NF]     = e0;
            ep[(size_t)(t0 + 4 * g + 1) * NF] = e1;
            ep[(size_t)(t0 + 4 * g + 2) * NF] = e2;
            ep[(size_t)(t0 + 4 * g + 3) * NF] = e3;
        }

        u64 k0 = pack2(c0, c0), k1 = pack2(c1, c1);
        u64 k2 = pack2(c2, c2), k3 = pack2(c3, c3);
        {   // tap-pair 0 of steps t,t+1 needs the OLD slot p+1 contents
            u64 w = W2[0];
            w = ffma2(k0, oldP1, w);
            w = ffma2(k1, oldQ1, w);
            w = ffma2(k2, P[(p + 2) & 7], w);
            w = ffma2(k3, Q[(p + 2) & 7], w);
            W2[0] = w;
        }
#pragma unroll
        for (int i = 1; i < 8; i++) {
            u64 w = W2[i];
            w = ffma2(k0, P[(p + 1 + i) & 7], w);
            w = ffma2(k1, Q[(p + 1 + i) & 7], w);
            w = ffma2(k2, P[(p + 2 + i) & 7], w);
            w = ffma2(k3, Q[(p + 2 + i) & 7], w);
            W2[i] = w;
        }
    }
}

__global__ void __launch_bounds__(128, 2)
nlms_kernel(const float* __restrict__ X, const float* __restrict__ Y,
            const float* __restrict__ Wp, float* __restrict__ out,
            int write_w)
{
    int gtid = blockIdx.x * blockDim.x + threadIdx.x;
    if (gtid >= NTHREAD) return;
    int h = gtid & 1;          // odd lane = unshifted stream, writer
    int seq = gtid >> 1;
    int b = seq / NF;
    int f = seq - b * NF;
    int off = 16 * (1 - h);

    size_t base = (size_t)b * NT * NF + f;
    const float* xp = X + base;
    const float* yp = Y + base;
    float* ep = out + base;

    u64 W2[8], P[8], Q[8];
#pragma unroll
    for (int i = 0; i < 8; i++) {
        int j = 16 * h + 2 * i;
        float w0 = Wp[((size_t)b * NL + j) * NF + f];
        float w1 = Wp[((size_t)b * NL + j + 1) * NF + f];
        W2[i] = pack2(w0, w1);
        P[i] = 0; Q[i] = 0;
    }
    float S = 0.f, G1 = 0.f, G2 = 0.f, G3 = 0.f;
    Carry cr = {0.f, 0.f, 0.f, 0.f, 0.f, 0.f};

    float xb0[16], xb1[16], xb2[16], yb0[16], yb1[16], yb2[16];
#pragma unroll
    for (int i = 0; i < 16; i++) { xb1[i] = 0.f; xb2[i] = 0.f; }

    float minv[16], g1s[12], g2s[8], g3s[4];

    pf_g(xb0, yb0, xp, yp, 0, off);   // block 0

    int t0 = 0;
    // Block n: cur = xb[n%3], old2 = xb[(n+1)%3] (block n-2; zeros for n<2).
    // Prologue consumes old2, carries captured, THEN prefetch n+1 into old2's
    // buffer, then serial. 125 blocks = 41*3 + 2.
#define ITER(XC, XO, YC, YO, PF)                                             \
    do {                                                                     \
        prologue(XC, XO, S, G1, G2, G3, cr, minv, g1s, g2s, g3s, h);         \
        float n33 = XO[15], n34 = XO[14], n35 = XO[13];                      \
        if (PF) pf_u(XO, YO, xp, yp, t0 + NSTEP, off);                       \
        serial4(W2, P, Q, XC, YC, minv, g1s, g2s, g3s, cr.xl1, ep, t0, h);   \
        cr.xl3 = XC[13]; cr.xl2 = XC[14]; cr.xl1 = XC[15];                   \
        cr.c33 = n33; cr.c34 = n34; cr.c35 = n35;                            \
        t0 += NSTEP;                                                         \
    } while (0)

#pragma unroll 1
    for (int mm = 0; mm < 41; mm++) {        // blocks 0..122
        ITER(xb0, xb1, yb0, yb1, 1);
        ITER(xb1, xb2, yb1, yb2, 1);
        ITER(xb2, xb0, yb2, yb0, 1);
    }
    ITER(xb0, xb1, yb0, yb1, 1);             // block 123 (prefetch 124)
    ITER(xb1, xb2, yb1, yb2, 0);             // block 124 (no prefetch)
#undef ITER

    if (write_w) {
        float* wf = out + (size_t)NB * NT * NF;
#pragma unroll
        for (int i = 0; i < 8; i++) {
            int j = 16 * h + 2 * i;
            float w0, w1;
            unpack2(W2[i], w0, w1);
            wf[((size_t)b * NL + j) * NF + f] = w0;
            wf[((size_t)b * NL + j + 1) * NF + f] = w1;
        }
    }
}

extern "C" void kernel_launch(void* const* d_in, const int* in_sizes, int n_in,
                              void* d_out, int out_size)
{
    const float* X  = (const float*)d_in[0];
    const float* Y  = (const float*)d_in[1];
    const float* Wp = (const float*)d_in[2];
    float* out = (float*)d_out;

    long long need = (long long)NB * NT * NF + (long long)NB * NL * NF;
    int write_w = ((long long)out_size >= need) ? 1 : 0;

    // 32832 threads (1026 warps), 128/block -> 257 blocks, 2 blocks/SM.
    nlms_kernel<<<257, 128>>>(X, Y, Wp, out, write_w);
}